// round 6
// baseline (speedup 1.0000x reference)
#include <cuda_runtime.h>
#include <stdint.h>

// Problem constants (fixed by the reference).
#define NPRE      6000
#define NPOST     2000
#define NB        94           // ceil(NPRE/64) column groups
#define NROWS     (NB * 64)    // 6016 padded rows
#define HB        32768        // score histogram buckets (scores in [0,1))
#define CAND_MAX  8192
#define BCAP      256          // per-bucket sort capacity
#define SCUT      (HB - 256)   // stash cut bucket
#define STASH_CAP 32768
#define TPB       256
#define BPS       4            // blocks per SM (co-resident)
#define NTILES    1152         // sum over cols g of ceil((g+1)*64/256)

// ---------------- persistent device scratch ---------------------------------
__device__ unsigned           g_barcnt;   // grid barrier (self-resetting)
__device__ unsigned           g_bargen;   // grid barrier generation (monotonic)
__device__ unsigned           g_hist[HB];
__device__ unsigned           g_cnt[HB];
__device__ unsigned           g_base[HB];
__device__ int                g_thresh;
__device__ int                g_nstash;
__device__ unsigned long long g_stash[STASH_CAP];
__device__ unsigned long long g_cand[CAND_MAX];
__device__ float g_y1[NROWS], g_x1[NROWS], g_y2[NROWS], g_x2[NROWS];
__device__ float g_pa[NROWS], g_scores[NROWS];
__device__ unsigned long long g_maskT[NB][NROWS];   // [col_group][row]
__device__ int                g_coldone[NB];
__device__ int                g_ticket;
__device__ int                g_kept[NPOST];
__device__ int                g_kcount;
__device__ int                g_done;

__device__ __forceinline__ int score_bucket(float s) {
    int b = (int)(s * 32768.0f);
    return max(0, min(HB - 1, b));
}

// software grid barrier; all blocks resident by construction
__device__ __forceinline__ void gbar(int nbk) {
    __syncthreads();
    if (threadIdx.x == 0) {
        unsigned gen = *(volatile unsigned*)&g_bargen;
        __threadfence();
        if (atomicAdd(&g_barcnt, 1u) == (unsigned)nbk - 1u) {
            g_barcnt = 0u;
            __threadfence();
            atomicAdd(&g_bargen, 1u);
        } else {
            while (*(volatile unsigned*)&g_bargen == gen) __nanosleep(32);
        }
        __threadfence();
    }
    __syncthreads();
}

__global__ __launch_bounds__(TPB, BPS)
void persist_k(const float4* __restrict__ enc4, const float4* __restrict__ anch4,
               const float4* __restrict__ s4, float* __restrict__ out,
               int n, int n4) {
    const int t   = threadIdx.x;
    const int bid = blockIdx.x;
    const int nbk = gridDim.x;
    const int gid = bid * TPB + t;
    const int gs  = nbk * TPB;

    __shared__ unsigned s_scan[TPB];
    __shared__ unsigned long long s_sort[BCAP];
    __shared__ float4 s_cb[64];
    __shared__ float  s_cp[64];
    __shared__ int s_kept[NPOST];
    __shared__ unsigned long long s_alive[NB];
    __shared__ unsigned long long s_col[64], s_gnext[64];
    __shared__ unsigned long long s_crossbuf[2], s_colOR, s_alivew;
    __shared__ int s_kc, s_tau;

    // ---- P0: zero state (barrier vars NOT touched) --------------------------
    for (int i = gid; i < HB; i += gs) { g_hist[i] = 0u; g_cnt[i] = 0u; }
    for (int i = gid; i < NB; i += gs) g_coldone[i] = 0;
    if (gid == 0) { g_nstash = 0; g_ticket = 0; g_done = 0; g_kcount = 0; }
    gbar(nbk);

    // ---- P1: histogram + stash of top-bucket candidates ---------------------
    for (int i = gid; i < n4; i += gs) {
        float4 v = s4[i];
        float e[4] = {v.x, v.y, v.z, v.w};
#pragma unroll
        for (int c = 0; c < 4; c++) {
            int b = score_bucket(e[c]);
            atomicAdd(&g_hist[b], 1u);
            if (b >= SCUT) {
                int p = atomicAdd(&g_nstash, 1);
                if (p < STASH_CAP) {
                    unsigned idx = (unsigned)(4 * i + c);
                    g_stash[p] = ((unsigned long long)__float_as_uint(e[c]) << 32)
                               | (unsigned long long)(0xFFFFFFFFu - idx);
                }
            }
        }
    }
    gbar(nbk);

    // ---- P2: threshold + per-bucket descending rank bases (block 0) ---------
    if (bid == 0) {
        int lo = HB - (t + 1) * 128;   // thread owns buckets [lo, lo+128); t=0 top
        unsigned sum = 0;
        const uint4* h4 = (const uint4*)g_hist;
#pragma unroll
        for (int k = 0; k < 32; k++) {
            uint4 u = h4[(lo >> 2) + k];
            sum += u.x + u.y + u.z + u.w;
        }
        s_scan[t] = sum;
        __syncthreads();
        for (int off = 1; off < TPB; off <<= 1) {
            unsigned v = (t >= off) ? s_scan[t - off] : 0u;
            __syncthreads();
            s_scan[t] += v;
            __syncthreads();
        }
        unsigned run = s_scan[t] - sum;   // count strictly above this chunk
        for (int b = 127; b >= 0; --b) {
            unsigned c = g_hist[lo + b];
            g_base[lo + b] = run;
            if (run < (unsigned)NPRE && run + c >= (unsigned)NPRE) g_thresh = lo + b;
            run += c;
        }
        if (t == TPB - 1 && s_scan[TPB - 1] < (unsigned)NPRE) g_thresh = 0;
    }
    gbar(nbk);

    // ---- P3: counting-sort scatter (stash fast path / full fallback) --------
    {
        int T = g_thresh;
        int ns = g_nstash;
        if (T >= SCUT && ns <= STASH_CAP) {
            for (int i = gid; i < ns; i += gs) {
                unsigned long long key = g_stash[i];
                int b = score_bucket(__uint_as_float((unsigned)(key >> 32)));
                if (b >= T) {
                    unsigned pos = g_base[b] + atomicAdd(&g_cnt[b], 1u);
                    if (pos < CAND_MAX) g_cand[pos] = key;
                }
            }
        } else {
            for (int i = gid; i < n4; i += gs) {
                float4 v = s4[i];
                float e[4] = {v.x, v.y, v.z, v.w};
#pragma unroll
                for (int c = 0; c < 4; c++) {
                    int b = score_bucket(e[c]);
                    if (b >= T) {
                        unsigned pos = g_base[b] + atomicAdd(&g_cnt[b], 1u);
                        if (pos < CAND_MAX) {
                            unsigned idx = (unsigned)(4 * i + c);
                            g_cand[pos] = ((unsigned long long)__float_as_uint(e[c]) << 32)
                                        | (unsigned long long)(0xFFFFFFFFu - idx);
                        }
                    }
                }
            }
        }
    }
    gbar(nbk);

    // ---- P4: per-bucket micro bitonic sorts (descending) --------------------
    {
        int T = g_thresh;
        for (int b = T + bid; b < HB; b += nbk) {
            unsigned base = g_base[b];
            if (base >= (unsigned)NPRE) continue;    // never read
            unsigned cnt = g_cnt[b];
            if (cnt <= 1) continue;
            int m = (cnt < (unsigned)BCAP) ? (int)cnt : BCAP;
            int kmax = 2; while (kmax < m) kmax <<= 1;
            for (int i = t; i < kmax; i += TPB) s_sort[i] = (i < m) ? g_cand[base + i] : 0ull;
            __syncthreads();
            for (int k = 2; k <= kmax; k <<= 1) {
                for (int j = k >> 1; j > 0; j >>= 1) {
                    for (int p = t; p < (kmax >> 1); p += TPB) {
                        int i = ((p & ~(j - 1)) << 1) | (p & (j - 1));
                        int x = i | j;
                        unsigned long long a = s_sort[i], bb = s_sort[x];
                        bool desc = ((i & k) == 0);
                        if (desc ? (a < bb) : (a > bb)) { s_sort[i] = bb; s_sort[x] = a; }
                    }
                    __syncthreads();
                }
            }
            for (int i = t; i < m; i += TPB) g_cand[base + i] = s_sort[i];
            __syncthreads();
        }
    }
    gbar(nbk);

    // ---- P5: decode top NPRE boxes into SoA ---------------------------------
    for (int r = gid; r < NROWS; r += gs) {
        float y1 = 0.f, x1 = 0.f, y2 = 0.f, x2 = 0.f, sc = 0.f;
        if (r < NPRE) {
            unsigned long long key = g_cand[r];
            unsigned idx = 0xFFFFFFFFu - (unsigned)(key & 0xFFFFFFFFull);
            if (idx < (unsigned)n) {
                sc = __uint_as_float((unsigned)(key >> 32));
                float4 a = anch4[idx];   // [y1, x1, y2, x2]
                float4 e = enc4[idx];    // [ty, tx, th, tw]
                float ha = a.z - a.x, wa = a.w - a.y;
                float cya = a.x + 0.5f * ha, cxa = a.y + 0.5f * wa;
                float cy = e.x * ha + cya;
                float cx = e.y * wa + cxa;
                float h  = expf(e.z) * ha;
                float w  = expf(e.w) * wa;
                y1 = cy - 0.5f * h; x1 = cx - 0.5f * w;
                y2 = cy + 0.5f * h; x2 = cx + 0.5f * w;
            }
        }
        g_y1[r] = y1; g_x1[r] = x1; g_y2[r] = y2; g_x2[r] = x2;
        g_pa[r] = 0.7f * (y2 - y1) * (x2 - x1);
        g_scores[r] = sc;
    }
    gbar(nbk);

    // ---- P6: overlapped mask producers (blocks>0) + NMS consumer (block 0) --
    if (bid == 0) {
        for (int i = t; i < NB; i += TPB) s_alive[i] = 0ull;
        if (t == 0) { s_crossbuf[0] = 0ull; s_crossbuf[1] = 0ull; s_colOR = 0ull; }
        __syncthreads();
        int kcount = 0;
        for (int g = 0; g < NB; ++g) {
            int base = g * 64;
            int nn = NPRE - base; if (nn > 64) nn = 64;
            int cur = g & 1, nxt = cur ^ 1;
            bool haveNext = (g + 1 < NB);
            if (t == 0) {   // wait for column g (and g+1 for prefetch/cross)
                int need = (g >> 2) + 1;
                while (*(volatile int*)&g_coldone[g] < need) __nanosleep(32);
                if (haveNext) {
                    int need2 = ((g + 1) >> 2) + 1;
                    while (*(volatile int*)&g_coldone[g + 1] < need2) __nanosleep(32);
                }
                __threadfence();
            }
            __syncthreads();
            // Phase A (role split): cols | next-col prefetch | next cross
            if (t < 64) {
                unsigned long long w = g_maskT[g][base + t];
                s_col[t] = w;
                if (w) atomicOr(&s_colOR, w);
            } else if (t < 128) {
                s_gnext[t - 64] = haveNext ? g_maskT[g + 1][base + (t - 64)] : 0ull;
            } else if (haveNext) {
                unsigned long long p = 0ull;
                for (int r = t - 128; r < base; r += TPB - 128)
                    if ((s_alive[r >> 6] >> (r & 63)) & 1ull) p |= g_maskT[g + 1][r];
                if (p) atomicOr(&s_crossbuf[nxt], p);
            }
            __syncthreads();
            // Phase B: decision
            unsigned long long cross = s_crossbuf[cur];
            unsigned long long colOR = s_colOR;
            unsigned long long rowmask = (nn == 64) ? ~0ull : ((1ull << nn) - 1ull);
            bool fast = (cross == 0ull && colOR == 0ull && kcount + nn <= NPOST);
            if (fast) {
                if (t < nn) s_kept[kcount + t] = base + t;
                if (t == 0) { s_kc = kcount + nn; s_alivew = rowmask; }
            } else if (t == 0) {
                unsigned long long avail = (~cross) & rowmask;
                unsigned long long alivew = 0ull;
                int kc = kcount;
                while (avail && kc < NPOST) {
                    int k1 = __ffsll((long long)avail) - 1;
                    unsigned long long r = avail & (avail - 1);
                    unsigned long long c1 = s_col[k1];
                    int k2 = -1, k3 = -1, k4 = -1;
                    unsigned long long c2 = 0, c3 = 0, c4 = 0;
                    if (r) { k2 = __ffsll((long long)r) - 1; c2 = s_col[k2]; r &= r - 1;
                        if (r) { k3 = __ffsll((long long)r) - 1; c3 = s_col[k3]; r &= r - 1;
                            if (r) { k4 = __ffsll((long long)r) - 1; c4 = s_col[k4]; r &= r - 1; } } }
                    unsigned long long m = c1;
                    s_kept[kc++] = base + k1; alivew |= 1ull << k1;
                    if (k2 >= 0 && kc < NPOST && !((m >> k2) & 1ull)) { s_kept[kc++] = base + k2; alivew |= 1ull << k2; m |= c2; }
                    if (k3 >= 0 && kc < NPOST && !((m >> k3) & 1ull)) { s_kept[kc++] = base + k3; alivew |= 1ull << k3; m |= c3; }
                    if (k4 >= 0 && kc < NPOST && !((m >> k4) & 1ull)) { s_kept[kc++] = base + k4; alivew |= 1ull << k4; m |= c4; }
                    avail = r & ~m;
                }
                s_kc = kc; s_alivew = alivew;
            }
            __syncthreads();
            // Phase C: combine + bookkeeping
            kcount = s_kc;
            unsigned long long aw = s_alivew;
            if (t < 64 && ((aw >> t) & 1ull)) {
                unsigned long long w = s_gnext[t];
                if (w) atomicOr(&s_crossbuf[nxt], w);
            }
            if (t == 0) { s_alive[g] = aw; s_crossbuf[cur] = 0ull; s_colOR = 0ull; }
            __syncthreads();
            if (kcount >= NPOST) break;
        }
        for (int i = t; i < kcount; i += TPB) g_kept[i] = s_kept[i];
        if (t == 0) { g_kcount = kcount; __threadfence(); g_done = 1; }
    } else {
        // producers: tiles of 256 rows x 64 cols, ticket order ~ column-ascending
        while (true) {
            if (t == 0) {
                int d = *(volatile int*)&g_done;
                s_tau = d ? NTILES : atomicAdd(&g_ticket, 1);
            }
            __syncthreads();
            int tau = s_tau;
            if (tau >= NTILES) break;
            // map tau -> (col g, row block rb): cols 4a..4a+3 have a+1 tiles each
            int a = (int)((sqrtf(1.0f + 2.0f * (float)tau) - 1.0f) * 0.5f);
            while (2 * (a + 1) * (a + 2) <= tau) a++;
            while (2 * a * (a + 1) > tau) a--;
            int rem = tau - 2 * a * (a + 1);
            int g  = 4 * a + rem / (a + 1);
            int rb = rem % (a + 1);
            int jbase = g * 64;
            if (t < 64) {
                int j = jbase + t;
                s_cb[t] = make_float4(g_y1[j], g_x1[j], g_y2[j], g_x2[j]);
                s_cp[t] = g_pa[j];
            }
            __syncthreads();
            int i = rb * TPB + t;
            if (i < jbase + 64) {
                float y1 = g_y1[i], x1 = g_x1[i], y2 = g_y2[i], x2 = g_x2[i];
                float pa = g_pa[i];
                unsigned long long m = 0ull;
                if (i < jbase) {
#pragma unroll 16
                    for (int c = 0; c < 64; c++) {
                        float4 cb = s_cb[c];
                        float iy1 = fmaxf(y1, cb.x), ix1 = fmaxf(x1, cb.y);
                        float iy2 = fminf(y2, cb.z), ix2 = fminf(x2, cb.w);
                        float dy = fmaxf(iy2 - iy1, 0.f), dx = fmaxf(ix2 - ix1, 0.f);
                        bool cond = fmaf(1.7f, dy * dx, -pa) > s_cp[c];
                        m |= ((unsigned long long)cond) << c;
                    }
                } else {   // diagonal rows: only c > i-jbase
                    for (int c = (i - jbase) + 1; c < 64; c++) {
                        float4 cb = s_cb[c];
                        float iy1 = fmaxf(y1, cb.x), ix1 = fmaxf(x1, cb.y);
                        float iy2 = fminf(y2, cb.z), ix2 = fminf(x2, cb.w);
                        float dy = fmaxf(iy2 - iy1, 0.f), dx = fmaxf(ix2 - ix1, 0.f);
                        bool cond = fmaf(1.7f, dy * dx, -pa) > s_cp[c];
                        m |= ((unsigned long long)cond) << c;
                    }
                }
                g_maskT[g][i] = m;
            }
            __syncthreads();
            if (t == 0) { __threadfence(); atomicAdd(&g_coldone[g], 1); }
        }
    }
    gbar(nbk);

    // ---- P7: write output ----------------------------------------------------
    for (int o = gid; o < NPOST; o += gs) {
        int kcount = g_kcount;
        if (o < kcount) {
            int i = g_kept[o];
            ((float4*)out)[o] = make_float4(g_y1[i], g_x1[i], g_y2[i], g_x2[i]);
            out[NPOST * 4 + o] = g_scores[i];
        } else {
            ((float4*)out)[o] = make_float4(0.f, 0.f, 0.f, 0.f);
            out[NPOST * 4 + o] = 0.f;
        }
    }
}

// ---------------- launch ----------------------------------------------------
extern "C" void kernel_launch(void* const* d_in, const int* in_sizes, int n_in,
                              void* d_out, int out_size) {
    const float* enc    = (const float*)d_in[0];  // encoded_bboxes [N,4]
    const float* anch   = (const float*)d_in[1];  // anchors        [N,4]
    const float* scores = (const float*)d_in[2];  // scores         [N]
    float* out = (float*)d_out;                   // 2000*4 boxes + 2000 scores
    int n = in_sizes[2];
    int n4 = n / 4;

    int dev = 0, sms = 0;
    cudaGetDevice(&dev);
    cudaDeviceGetAttribute(&sms, cudaDevAttrMultiProcessorCount, dev);
    if (sms < 2) sms = 2;

    // one persistent kernel: BPS co-resident blocks per SM
    persist_k<<<sms * BPS, TPB>>>((const float4*)enc, (const float4*)anch,
                                  (const float4*)scores, out, n, n4);
}

// round 7
// speedup vs baseline: 1.0095x; 1.0095x over previous
#include <cuda_runtime.h>
#include <stdint.h>

// Problem constants (fixed by the reference).
#define NPRE      6000
#define NPOST     2000
#define NB        94           // ceil(NPRE/64) column groups
#define NROWS     (NB * 64)    // 6016 padded rows
#define HB        32768        // score histogram buckets (scores in [0,1))
#define CAND_MAX  8192
#define BCAP      256          // per-bucket sort capacity
#define SCUT      (HB - 256)   // stash cut bucket
#define STASH_CAP 32768
#define TPB       256
#define BPS       4            // blocks per SM (co-resident)
#define NTILES    1152         // sum over cols g of ceil((g+1)*64/256)
#define SLOCAL    192          // per-block stash buffer

// ---------------- persistent device scratch ---------------------------------
__device__ unsigned           g_barcnt;
__device__ unsigned           g_padA[63];   // keep barcnt/bargen on separate lines
__device__ unsigned           g_bargen;
__device__ unsigned           g_padB[63];
__device__ unsigned           g_hist[HB];
__device__ unsigned           g_cnt[HB];
__device__ unsigned           g_base[HB];
__device__ int                g_thresh;
__device__ int                g_nstash;
__device__ unsigned long long g_stash[STASH_CAP];
__device__ unsigned long long g_cand[CAND_MAX];
__device__ float g_y1[NROWS], g_x1[NROWS], g_y2[NROWS], g_x2[NROWS];
__device__ float g_pa[NROWS], g_scores[NROWS];
__device__ unsigned long long g_maskT[NB][NROWS];   // [col_group][row]
__device__ int                g_coldone[NB];
__device__ int                g_ticket;
__device__ int                g_kept[NPOST];
__device__ int                g_kcount;
__device__ int                g_done;

__device__ __forceinline__ int score_bucket(float s) {
    int b = (int)(s * 32768.0f);
    return max(0, min(HB - 1, b));
}

// software grid barrier; all blocks resident by construction. Busy-poll.
__device__ __forceinline__ void gbar(int nbk) {
    __syncthreads();
    if (threadIdx.x == 0) {
        unsigned gen = *(volatile unsigned*)&g_bargen;
        __threadfence();
        if (atomicAdd(&g_barcnt, 1u) == (unsigned)nbk - 1u) {
            g_barcnt = 0u;
            __threadfence();
            atomicAdd(&g_bargen, 1u);
        } else {
            while (*(volatile unsigned*)&g_bargen == gen) { }
        }
        __threadfence();
    }
    __syncthreads();
}

__global__ __launch_bounds__(TPB, BPS)
void persist_k(const float4* __restrict__ enc4, const float4* __restrict__ anch4,
               const float4* __restrict__ s4, float* __restrict__ out,
               int n, int n4) {
    const int t   = threadIdx.x;
    const int bid = blockIdx.x;
    const int nbk = gridDim.x;
    const int gid = bid * TPB + t;
    const int gs  = nbk * TPB;

    __shared__ unsigned s_scan[TPB];
    __shared__ unsigned long long s_sort[BCAP];
    __shared__ unsigned long long s_stash[SLOCAL];
    __shared__ int s_scnt, s_sbase;
    __shared__ float4 s_cb[64];
    __shared__ float  s_cp[64];
    __shared__ int s_kept[NPOST];
    __shared__ unsigned long long s_alive[NB];
    __shared__ unsigned long long s_col[64], s_gnext[64];
    __shared__ unsigned long long s_crossbuf[2], s_colOR, s_alivew;
    __shared__ int s_kc, s_tau;

    // ---- P0: zero state (barrier vars NOT touched) --------------------------
    for (int i = gid; i < HB; i += gs) { g_hist[i] = 0u; g_cnt[i] = 0u; }
    for (int i = gid; i < NB; i += gs) g_coldone[i] = 0;
    for (int r = NPRE + gid; r < NROWS; r += gs) {   // pad rows stay zero boxes
        g_y1[r] = 0.f; g_x1[r] = 0.f; g_y2[r] = 0.f; g_x2[r] = 0.f;
        g_pa[r] = 0.f; g_scores[r] = 0.f;
    }
    if (gid == 0) { g_nstash = 0; g_ticket = 0; g_done = 0; g_kcount = 0; }
    if (t == 0) s_scnt = 0;
    gbar(nbk);

    // ---- P1: histogram + block-aggregated stash of top-bucket candidates ----
    for (int i = gid; i < n4; i += gs) {
        float4 v = s4[i];
        float e[4] = {v.x, v.y, v.z, v.w};
#pragma unroll
        for (int c = 0; c < 4; c++) {
            int b = score_bucket(e[c]);
            atomicAdd(&g_hist[b], 1u);
            if (b >= SCUT) {
                unsigned idx = (unsigned)(4 * i + c);
                unsigned long long key =
                    ((unsigned long long)__float_as_uint(e[c]) << 32)
                  | (unsigned long long)(0xFFFFFFFFu - idx);
                int p = atomicAdd(&s_scnt, 1);
                if (p < SLOCAL) s_stash[p] = key;
                else {                         // overflow fallback (rare)
                    int q = atomicAdd(&g_nstash, 1);
                    if (q < STASH_CAP) g_stash[q] = key;
                }
            }
        }
    }
    __syncthreads();
    {   // flush block-local stash with ONE hot atomic per block
        int cnt = s_scnt; if (cnt > SLOCAL) cnt = SLOCAL;
        if (t == 0) s_sbase = atomicAdd(&g_nstash, cnt);
        __syncthreads();
        for (int i = t; i < cnt; i += TPB) {
            int q = s_sbase + i;
            if (q < STASH_CAP) g_stash[q] = s_stash[i];
        }
    }
    gbar(nbk);

    // ---- P2: threshold + per-bucket descending rank bases (block 0) ---------
    if (bid == 0) {
        int lo = HB - (t + 1) * 128;   // thread owns buckets [lo, lo+128); t=0 top
        unsigned sum = 0;
        const uint4* h4 = (const uint4*)g_hist;
#pragma unroll
        for (int k = 0; k < 32; k++) {
            uint4 u = h4[(lo >> 2) + k];
            sum += u.x + u.y + u.z + u.w;
        }
        s_scan[t] = sum;
        __syncthreads();
        for (int off = 1; off < TPB; off <<= 1) {
            unsigned v = (t >= off) ? s_scan[t - off] : 0u;
            __syncthreads();
            s_scan[t] += v;
            __syncthreads();
        }
        unsigned run = s_scan[t] - sum;   // count strictly above this chunk
        for (int b = 127; b >= 0; --b) {
            unsigned c = g_hist[lo + b];
            g_base[lo + b] = run;
            if (run < (unsigned)NPRE && run + c >= (unsigned)NPRE) g_thresh = lo + b;
            run += c;
        }
        if (t == TPB - 1 && s_scan[TPB - 1] < (unsigned)NPRE) g_thresh = 0;
    }
    gbar(nbk);

    // ---- P3: counting-sort scatter (stash fast path / full fallback) --------
    {
        int T = g_thresh;
        int ns = g_nstash;
        if (T >= SCUT && ns <= STASH_CAP) {
            for (int i = gid; i < ns; i += gs) {
                unsigned long long key = g_stash[i];
                int b = score_bucket(__uint_as_float((unsigned)(key >> 32)));
                if (b >= T) {
                    unsigned pos = g_base[b] + atomicAdd(&g_cnt[b], 1u);
                    if (pos < CAND_MAX) g_cand[pos] = key;
                }
            }
        } else {
            for (int i = gid; i < n4; i += gs) {
                float4 v = s4[i];
                float e[4] = {v.x, v.y, v.z, v.w};
#pragma unroll
                for (int c = 0; c < 4; c++) {
                    int b = score_bucket(e[c]);
                    if (b >= T) {
                        unsigned pos = g_base[b] + atomicAdd(&g_cnt[b], 1u);
                        if (pos < CAND_MAX) {
                            unsigned idx = (unsigned)(4 * i + c);
                            g_cand[pos] = ((unsigned long long)__float_as_uint(e[c]) << 32)
                                        | (unsigned long long)(0xFFFFFFFFu - idx);
                        }
                    }
                }
            }
        }
    }
    gbar(nbk);

    // ---- P4: per-bucket micro bitonic sort FUSED with decode ----------------
    {
        int T = g_thresh;
        for (int b = T + bid; b < HB; b += nbk) {
            unsigned base = g_base[b];
            if (base >= (unsigned)NPRE) continue;    // never read
            unsigned cnt = g_cnt[b];
            if (cnt == 0) continue;
            int m = (cnt < (unsigned)BCAP) ? (int)cnt : BCAP;
            if (m > 1) {
                int kmax = 2; while (kmax < m) kmax <<= 1;
                for (int i = t; i < kmax; i += TPB)
                    s_sort[i] = (i < m) ? g_cand[base + i] : 0ull;
                __syncthreads();
                for (int k = 2; k <= kmax; k <<= 1) {
                    for (int j = k >> 1; j > 0; j >>= 1) {
                        for (int p = t; p < (kmax >> 1); p += TPB) {
                            int i = ((p & ~(j - 1)) << 1) | (p & (j - 1));
                            int x = i | j;
                            unsigned long long a = s_sort[i], bb = s_sort[x];
                            bool desc = ((i & k) == 0);
                            if (desc ? (a < bb) : (a > bb)) { s_sort[i] = bb; s_sort[x] = a; }
                        }
                        __syncthreads();
                    }
                }
            }
            // decode ranks [base, base+cnt) ∩ [0, NPRE) straight from s_sort
            int lim = (int)cnt;
            if (base + lim > (unsigned)NPRE) lim = NPRE - base;
            if (base + lim > (unsigned)CAND_MAX) lim = CAND_MAX - base;
            for (int i = t; i < lim; i += TPB) {
                unsigned long long key = (m > 1 && i < m) ? s_sort[i] : g_cand[base + i];
                int r = (int)base + i;
                float y1 = 0.f, x1 = 0.f, y2 = 0.f, x2 = 0.f, sc = 0.f;
                unsigned idx = 0xFFFFFFFFu - (unsigned)(key & 0xFFFFFFFFull);
                if (idx < (unsigned)n) {
                    sc = __uint_as_float((unsigned)(key >> 32));
                    float4 a = anch4[idx];   // [y1, x1, y2, x2]
                    float4 e = enc4[idx];    // [ty, tx, th, tw]
                    float ha = a.z - a.x, wa = a.w - a.y;
                    float cya = a.x + 0.5f * ha, cxa = a.y + 0.5f * wa;
                    float cy = e.x * ha + cya;
                    float cx = e.y * wa + cxa;
                    float h  = expf(e.z) * ha;
                    float w  = expf(e.w) * wa;
                    y1 = cy - 0.5f * h; x1 = cx - 0.5f * w;
                    y2 = cy + 0.5f * h; x2 = cx + 0.5f * w;
                }
                g_y1[r] = y1; g_x1[r] = x1; g_y2[r] = y2; g_x2[r] = x2;
                g_pa[r] = 0.7f * (y2 - y1) * (x2 - x1);
                g_scores[r] = sc;
            }
            __syncthreads();
        }
    }
    gbar(nbk);

    // ---- P6: overlapped mask producers (blocks>0) + NMS consumer (block 0) --
    if (bid == 0) {
        for (int i = t; i < NB; i += TPB) s_alive[i] = 0ull;
        if (t == 0) { s_crossbuf[0] = 0ull; s_crossbuf[1] = 0ull; s_colOR = 0ull; }
        __syncthreads();
        int kcount = 0;
        for (int g = 0; g < NB; ++g) {
            int base = g * 64;
            int nn = NPRE - base; if (nn > 64) nn = 64;
            int cur = g & 1, nxt = cur ^ 1;
            bool haveNext = (g + 1 < NB);
            if (t == 0) {   // BUSY-POLL for column g (and g+1) readiness
                int need = (g >> 2) + 1;
                while (*(volatile int*)&g_coldone[g] < need) { }
                if (haveNext) {
                    int need2 = ((g + 1) >> 2) + 1;
                    while (*(volatile int*)&g_coldone[g + 1] < need2) { }
                }
                __threadfence();
            }
            __syncthreads();
            // Phase A (role split): cols | next-col prefetch | next cross
            if (t < 64) {
                unsigned long long w = g_maskT[g][base + t];
                s_col[t] = w;
                if (w) atomicOr(&s_colOR, w);
            } else if (t < 128) {
                s_gnext[t - 64] = haveNext ? g_maskT[g + 1][base + (t - 64)] : 0ull;
            } else if (haveNext) {
                unsigned long long p = 0ull;
                for (int r = t - 128; r < base; r += TPB - 128)
                    if ((s_alive[r >> 6] >> (r & 63)) & 1ull) p |= g_maskT[g + 1][r];
                if (p) atomicOr(&s_crossbuf[nxt], p);
            }
            __syncthreads();
            // Phase B: decision
            unsigned long long cross = s_crossbuf[cur];
            unsigned long long colOR = s_colOR;
            unsigned long long rowmask = (nn == 64) ? ~0ull : ((1ull << nn) - 1ull);
            bool fast = (cross == 0ull && colOR == 0ull && kcount + nn <= NPOST);
            if (fast) {
                if (t < nn) s_kept[kcount + t] = base + t;
                if (t == 0) { s_kc = kcount + nn; s_alivew = rowmask; }
            } else if (t == 0) {
                unsigned long long avail = (~cross) & rowmask;
                unsigned long long alivew = 0ull;
                int kc = kcount;
                while (avail && kc < NPOST) {
                    int k1 = __ffsll((long long)avail) - 1;
                    unsigned long long r = avail & (avail - 1);
                    unsigned long long c1 = s_col[k1];
                    int k2 = -1, k3 = -1, k4 = -1;
                    unsigned long long c2 = 0, c3 = 0, c4 = 0;
                    if (r) { k2 = __ffsll((long long)r) - 1; c2 = s_col[k2]; r &= r - 1;
                        if (r) { k3 = __ffsll((long long)r) - 1; c3 = s_col[k3]; r &= r - 1;
                            if (r) { k4 = __ffsll((long long)r) - 1; c4 = s_col[k4]; r &= r - 1; } } }
                    unsigned long long m = c1;
                    s_kept[kc++] = base + k1; alivew |= 1ull << k1;
                    if (k2 >= 0 && kc < NPOST && !((m >> k2) & 1ull)) { s_kept[kc++] = base + k2; alivew |= 1ull << k2; m |= c2; }
                    if (k3 >= 0 && kc < NPOST && !((m >> k3) & 1ull)) { s_kept[kc++] = base + k3; alivew |= 1ull << k3; m |= c3; }
                    if (k4 >= 0 && kc < NPOST && !((m >> k4) & 1ull)) { s_kept[kc++] = base + k4; alivew |= 1ull << k4; m |= c4; }
                    avail = r & ~m;
                }
                s_kc = kc; s_alivew = alivew;
            }
            __syncthreads();
            // Phase C: combine + bookkeeping
            kcount = s_kc;
            unsigned long long aw = s_alivew;
            if (t < 64 && ((aw >> t) & 1ull)) {
                unsigned long long w = s_gnext[t];
                if (w) atomicOr(&s_crossbuf[nxt], w);
            }
            if (t == 0) { s_alive[g] = aw; s_crossbuf[cur] = 0ull; s_colOR = 0ull; }
            __syncthreads();
            if (kcount >= NPOST) break;
        }
        for (int i = t; i < kcount; i += TPB) g_kept[i] = s_kept[i];
        if (t == 0) { g_kcount = kcount; __threadfence(); g_done = 1; }
    } else {
        // producers: tiles of 256 rows x 64 cols, ticket order = column-ascending
        while (true) {
            if (t == 0) {
                int d = *(volatile int*)&g_done;
                s_tau = d ? NTILES : atomicAdd(&g_ticket, 1);
            }
            __syncthreads();
            int tau = s_tau;
            if (tau >= NTILES) break;
            // map tau -> (col g, row block rb): cols 4a..4a+3 have a+1 tiles each
            int a = (int)((sqrtf(1.0f + 2.0f * (float)tau) - 1.0f) * 0.5f);
            while (2 * (a + 1) * (a + 2) <= tau) a++;
            while (2 * a * (a + 1) > tau) a--;
            int rem = tau - 2 * a * (a + 1);
            int g  = 4 * a + rem / (a + 1);
            int rb = rem % (a + 1);
            int jbase = g * 64;
            if (t < 64) {
                int j = jbase + t;
                s_cb[t] = make_float4(g_y1[j], g_x1[j], g_y2[j], g_x2[j]);
                s_cp[t] = g_pa[j];
            }
            __syncthreads();
            int i = rb * TPB + t;
            if (i < jbase + 64) {
                float y1 = g_y1[i], x1 = g_x1[i], y2 = g_y2[i], x2 = g_x2[i];
                float pa = g_pa[i];
                unsigned long long m = 0ull;
                if (i < jbase) {
#pragma unroll 16
                    for (int c = 0; c < 64; c++) {
                        float4 cb = s_cb[c];
                        float iy1 = fmaxf(y1, cb.x), ix1 = fmaxf(x1, cb.y);
                        float iy2 = fminf(y2, cb.z), ix2 = fminf(x2, cb.w);
                        float dy = fmaxf(iy2 - iy1, 0.f), dx = fmaxf(ix2 - ix1, 0.f);
                        bool cond = fmaf(1.7f, dy * dx, -pa) > s_cp[c];
                        m |= ((unsigned long long)cond) << c;
                    }
                } else {   // diagonal rows: only c > i-jbase
                    for (int c = (i - jbase) + 1; c < 64; c++) {
                        float4 cb = s_cb[c];
                        float iy1 = fmaxf(y1, cb.x), ix1 = fmaxf(x1, cb.y);
                        float iy2 = fminf(y2, cb.z), ix2 = fminf(x2, cb.w);
                        float dy = fmaxf(iy2 - iy1, 0.f), dx = fmaxf(ix2 - ix1, 0.f);
                        bool cond = fmaf(1.7f, dy * dx, -pa) > s_cp[c];
                        m |= ((unsigned long long)cond) << c;
                    }
                }
                g_maskT[g][i] = m;
            }
            __syncthreads();
            if (t == 0) { __threadfence(); atomicAdd(&g_coldone[g], 1); }
        }
    }
    gbar(nbk);

    // ---- P7: write output ----------------------------------------------------
    for (int o = gid; o < NPOST; o += gs) {
        int kcount = g_kcount;
        if (o < kcount) {
            int i = g_kept[o];
            ((float4*)out)[o] = make_float4(g_y1[i], g_x1[i], g_y2[i], g_x2[i]);
            out[NPOST * 4 + o] = g_scores[i];
        } else {
            ((float4*)out)[o] = make_float4(0.f, 0.f, 0.f, 0.f);
            out[NPOST * 4 + o] = 0.f;
        }
    }
}

// ---------------- launch ----------------------------------------------------
extern "C" void kernel_launch(void* const* d_in, const int* in_sizes, int n_in,
                              void* d_out, int out_size) {
    const float* enc    = (const float*)d_in[0];  // encoded_bboxes [N,4]
    const float* anch   = (const float*)d_in[1];  // anchors        [N,4]
    const float* scores = (const float*)d_in[2];  // scores         [N]
    float* out = (float*)d_out;                   // 2000*4 boxes + 2000 scores
    int n = in_sizes[2];
    int n4 = n / 4;

    int dev = 0, sms = 0;
    cudaGetDevice(&dev);
    cudaDeviceGetAttribute(&sms, cudaDevAttrMultiProcessorCount, dev);
    if (sms < 2) sms = 2;

    // one persistent kernel: BPS co-resident blocks per SM
    persist_k<<<sms * BPS, TPB>>>((const float4*)enc, (const float4*)anch,
                                  (const float4*)scores, out, n, n4);
}

// round 8
// speedup vs baseline: 1.2801x; 1.2681x over previous
#include <cuda_runtime.h>
#include <stdint.h>

// Problem constants (fixed by the reference).
#define NPRE     6000
#define NPOST    2000
#define NB       94          // ceil(NPRE/64)
#define NROWS    (NB * 64)   // 6016, padded
#define HB       32768       // score histogram buckets (scores in [0,1))
#define CAND_MAX 8192
#define BCAP     256         // per-bucket sort capacity
#define SCUT     (HB - 256)  // stash cut bucket
#define STASH_CAP 32768
#define SLOCAL   256         // per-block stash buffer

// ---------------- persistent device scratch ---------------------------------
__device__ unsigned           g_hist[HB];
__device__ unsigned           g_cnt[HB];
__device__ unsigned           g_base[HB];   // descending exclusive rank base
__device__ int                g_thresh;
__device__ int                g_nstash;
__device__ unsigned long long g_stash[STASH_CAP];
__device__ unsigned long long g_cand[CAND_MAX];
// SoA boxes (padded rows >= NPRE stay zero)
__device__ float              g_y1[NROWS], g_x1[NROWS], g_y2[NROWS], g_x2[NROWS];
__device__ float              g_pa[NROWS];      // 0.7f * area
__device__ float              g_scores[NROWS];
// transposed mask: g_maskT[col_group][row]
__device__ unsigned long long g_maskT[NB][NROWS];
__device__ unsigned long long g_alive[NB];
__device__ int                g_kept[NPOST];
__device__ int                g_kcount;
__device__ int                g_done;

__device__ __forceinline__ int score_bucket(float s) {
    int b = (int)(s * 32768.0f);
    return max(0, min(HB - 1, b));
}

// ---------------- K1: zero histograms + state + pad rows --------------------
__global__ void zero_k() {
    int i = blockIdx.x * blockDim.x + threadIdx.x;
    if (i < HB) { g_hist[i] = 0u; g_cnt[i] = 0u; }
    if (i < NB) g_alive[i] = 0ull;
    if (i < NROWS - NPRE) {      // pad rows: zero boxes forever
        int r = NPRE + i;
        g_y1[r] = 0.f; g_x1[r] = 0.f; g_y2[r] = 0.f; g_x2[r] = 0.f;
        g_pa[r] = 0.f; g_scores[r] = 0.f;
    }
    if (i == 0) { g_kcount = 0; g_done = 0; g_nstash = 0; }
}

// ---------------- K2: histogram + block-aggregated stash --------------------
__global__ void hist_stash_k(const float4* __restrict__ s4, int n4) {
    __shared__ unsigned long long s_stash[SLOCAL];
    __shared__ int s_scnt, s_sbase;
    if (threadIdx.x == 0) s_scnt = 0;
    __syncthreads();
    int i = blockIdx.x * blockDim.x + threadIdx.x;
    int stride = gridDim.x * blockDim.x;
    for (; i < n4; i += stride) {
        float4 v = s4[i];
        float e[4] = {v.x, v.y, v.z, v.w};
#pragma unroll
        for (int c = 0; c < 4; c++) {
            int b = score_bucket(e[c]);
            atomicAdd(&g_hist[b], 1u);
            if (b >= SCUT) {
                unsigned idx = (unsigned)(4 * i + c);
                unsigned long long key =
                    ((unsigned long long)__float_as_uint(e[c]) << 32)
                  | (unsigned long long)(0xFFFFFFFFu - idx);
                int p = atomicAdd(&s_scnt, 1);
                if (p < SLOCAL) s_stash[p] = key;
                else {                        // rare overflow: direct global
                    int q = atomicAdd(&g_nstash, 1);
                    if (q < STASH_CAP) g_stash[q] = key;
                }
            }
        }
    }
    __syncthreads();
    int cnt = s_scnt; if (cnt > SLOCAL) cnt = SLOCAL;
    if (threadIdx.x == 0) s_sbase = (cnt > 0) ? atomicAdd(&g_nstash, cnt) : 0;
    __syncthreads();
    for (int k = threadIdx.x; k < cnt; k += blockDim.x) {
        int q = s_sbase + k;
        if (q < STASH_CAP) g_stash[q] = s_stash[k];
    }
}

// ---------------- K3: threshold + per-bucket rank bases ---------------------
__global__ void thresh_k() {
    __shared__ unsigned s[1024];
    int t = threadIdx.x;
    int lo = HB - (t + 1) * 32;  // thread owns buckets [lo, lo+32); t=0 = top
    unsigned cnts[32];
    const uint4* h4 = (const uint4*)g_hist;
#pragma unroll
    for (int k = 0; k < 8; k++) {
        uint4 u = h4[(lo >> 2) + k];
        cnts[4 * k + 0] = u.x; cnts[4 * k + 1] = u.y;
        cnts[4 * k + 2] = u.z; cnts[4 * k + 3] = u.w;
    }
    unsigned sum = 0;
#pragma unroll
    for (int b = 0; b < 32; b++) sum += cnts[b];
    s[t] = sum;
    __syncthreads();
    for (int off = 1; off < 1024; off <<= 1) {
        unsigned v = (t >= off) ? s[t - off] : 0u;
        __syncthreads();
        s[t] += v;
        __syncthreads();
    }
    unsigned run = s[t] - sum;   // count strictly above this chunk
    for (int b = 31; b >= 0; --b) {
        g_base[lo + b] = run;
        unsigned c = cnts[b];
        if (run < (unsigned)NPRE && run + c >= (unsigned)NPRE) g_thresh = lo + b;
        run += c;
    }
    if (t == 1023 && s[1023] < (unsigned)NPRE) g_thresh = 0;  // degenerate
}

// ---------------- K4: counting-sort scatter (stash fast path / fallback) ----
__global__ void compact_k(const float4* __restrict__ s4, int n4) {
    int T = g_thresh;
    int ns = g_nstash;
    bool valid = (T >= SCUT) && (ns <= STASH_CAP);
    int tid = blockIdx.x * blockDim.x + threadIdx.x;
    int stride = gridDim.x * blockDim.x;
    if (valid) {
        for (int i = tid; i < ns; i += stride) {
            unsigned long long key = g_stash[i];
            int b = score_bucket(__uint_as_float((unsigned)(key >> 32)));
            if (b >= T) {
                unsigned pos = g_base[b] + atomicAdd(&g_cnt[b], 1u);
                if (pos < CAND_MAX) g_cand[pos] = key;
            }
        }
    } else {
        for (int i = tid; i < n4; i += stride) {
            float4 v = s4[i];
            float e[4] = {v.x, v.y, v.z, v.w};
#pragma unroll
            for (int c = 0; c < 4; c++) {
                int b = score_bucket(e[c]);
                if (b >= T) {
                    unsigned pos = g_base[b] + atomicAdd(&g_cnt[b], 1u);
                    if (pos < CAND_MAX) {
                        unsigned idx = (unsigned)(4 * i + c);
                        g_cand[pos] = ((unsigned long long)__float_as_uint(e[c]) << 32)
                                    | (unsigned long long)(0xFFFFFFFFu - idx);
                    }
                }
            }
        }
    }
}

// ---------------- K5: per-bucket bitonic sort FUSED with decode -------------
__global__ void bsort_decode_k(const float* __restrict__ enc,
                               const float* __restrict__ anch, int n) {
    __shared__ unsigned long long s[BCAP];
    int T = g_thresh;
    int t = threadIdx.x;                           // 128 threads
    for (int b = T + blockIdx.x; b < HB; b += gridDim.x) {
        unsigned base = g_base[b];
        if (base >= (unsigned)NPRE) continue;      // ranks never read
        unsigned cnt = g_cnt[b];
        if (cnt == 0) continue;
        int m = (cnt < (unsigned)BCAP) ? (int)cnt : BCAP;
        if (m > 1) {
            int kmax = 2; while (kmax < m) kmax <<= 1;
            for (int i = t; i < kmax; i += 128) s[i] = (i < m) ? g_cand[base + i] : 0ull;
            __syncthreads();
            for (int k = 2; k <= kmax; k <<= 1) {
                for (int j = k >> 1; j > 0; j >>= 1) {
                    for (int p = t; p < (kmax >> 1); p += 128) {
                        int i = ((p & ~(j - 1)) << 1) | (p & (j - 1));
                        int x = i | j;
                        unsigned long long a = s[i], bb = s[x];
                        bool desc = ((i & k) == 0);
                        if (desc ? (a < bb) : (a > bb)) { s[i] = bb; s[x] = a; }
                    }
                    __syncthreads();
                }
            }
        }
        // decode ranks [base, base+cnt) ∩ [0, NPRE) straight from shared
        int lim = (int)cnt;
        if (base + lim > (unsigned)NPRE) lim = NPRE - (int)base;
        if (base + lim > (unsigned)CAND_MAX) lim = CAND_MAX - (int)base;
        for (int i = t; i < lim; i += 128) {
            unsigned long long key = (m > 1 && i < m) ? s[i] : g_cand[base + i];
            int r = (int)base + i;
            float y1 = 0.f, x1 = 0.f, y2 = 0.f, x2 = 0.f, sc = 0.f;
            unsigned idx = 0xFFFFFFFFu - (unsigned)(key & 0xFFFFFFFFull);
            if (idx < (unsigned)n) {
                sc = __uint_as_float((unsigned)(key >> 32));
                float4 a = ((const float4*)anch)[idx];   // [y1, x1, y2, x2]
                float4 e = ((const float4*)enc)[idx];    // [ty, tx, th, tw]
                float ha = a.z - a.x, wa = a.w - a.y;
                float cya = a.x + 0.5f * ha, cxa = a.y + 0.5f * wa;
                float cy = e.x * ha + cya;
                float cx = e.y * wa + cxa;
                float h  = expf(e.z) * ha;
                float w  = expf(e.w) * wa;
                y1 = cy - 0.5f * h; x1 = cx - 0.5f * w;
                y2 = cy + 0.5f * h; x2 = cx + 0.5f * w;
            }
            g_y1[r] = y1; g_x1[r] = x1; g_y2[r] = y2; g_x2[r] = x2;
            g_pa[r] = 0.7f * (y2 - y1) * (x2 - x1);
            g_scores[r] = sc;
        }
        __syncthreads();
    }
}

// ---------------- K6: IoU bitmask, transposed coalesced writes --------------
// iou > 0.7  <=>  1.7*inter > 0.7*areaA + 0.7*areaB
__global__ void mask_k(int col0) {
    if (*(volatile int*)&g_done) return;
    int bx = col0 + blockIdx.x;
    int by = blockIdx.y;
    if (bx >= NB || by > bx) return;

    __shared__ float4 colb[64];
    __shared__ float  colp[64];
    int t = threadIdx.x;
    int j = bx * 64 + t;
    colb[t] = make_float4(g_y1[j], g_x1[j], g_y2[j], g_x2[j]);
    colp[t] = g_pa[j];
    __syncthreads();

    int i = by * 64 + t;
    float y1 = g_y1[i], x1 = g_x1[i], y2 = g_y2[i], x2 = g_x2[i];
    float pa = g_pa[i];
    unsigned long long m = 0ull;

    if (bx > by) {
#pragma unroll 16
        for (int c = 0; c < 64; c++) {
            float4 cb = colb[c];
            float iy1 = fmaxf(y1, cb.x), ix1 = fmaxf(x1, cb.y);
            float iy2 = fminf(y2, cb.z), ix2 = fminf(x2, cb.w);
            float dy = fmaxf(iy2 - iy1, 0.f), dx = fmaxf(ix2 - ix1, 0.f);
            bool cond = fmaf(1.7f, dy * dx, -pa) > colp[c];
            m |= ((unsigned long long)cond) << c;
        }
    } else {  // diagonal block: only c > t
        for (int c = t + 1; c < 64; c++) {
            float4 cb = colb[c];
            float iy1 = fmaxf(y1, cb.x), ix1 = fmaxf(x1, cb.y);
            float iy2 = fminf(y2, cb.z), ix2 = fminf(x2, cb.w);
            float dy = fmaxf(iy2 - iy1, 0.f), dx = fmaxf(ix2 - ix1, 0.f);
            bool cond = fmaf(1.7f, dy * dx, -pa) > colp[c];
            m |= ((unsigned long long)cond) << c;
        }
    }
    g_maskT[bx][i] = m;   // coalesced across t
}

// ---------------- K7: NMS partial reduce (role-split pipelined) -------------
__global__ void nms_part_k(int g0, int g1) {
    if (*(volatile int*)&g_done) return;
    __shared__ int                s_kept[NPOST];
    __shared__ unsigned long long s_alive[NB];
    __shared__ unsigned long long s_col[64];
    __shared__ unsigned long long s_gnext[64];
    __shared__ unsigned long long s_crossbuf[2];
    __shared__ unsigned long long s_colOR;
    __shared__ unsigned long long s_alivew;
    __shared__ int s_kc;
    int t = threadIdx.x;                       // 256 threads
    int kcount = g_kcount;
    for (int i = t; i < kcount; i += 256) s_kept[i] = g_kept[i];
    for (int i = t; i < NB; i += 256) s_alive[i] = g_alive[i];
    if (t == 0) { s_crossbuf[0] = 0ull; s_crossbuf[1] = 0ull; s_colOR = 0ull; }
    __syncthreads();
    // prologue: cross for g0 over rows < g0*64 (alive only)
    {
        unsigned long long p = 0ull;
        for (int r = t; r < g0 * 64; r += 256)
            if ((s_alive[r >> 6] >> (r & 63)) & 1ull) p |= g_maskT[g0][r];
        if (p) atomicOr(&s_crossbuf[g0 & 1], p);
    }
    __syncthreads();

    if (g1 > NB) g1 = NB;
    for (int g = g0; g < g1; ++g) {
        int base = g * 64;
        int n = NPRE - base; if (n > 64) n = 64;
        int cur = g & 1, nxt = cur ^ 1;
        bool haveNext = (g + 1 < NB);
        // ---- Phase A (role split): current cols | next-col prefetch | next cross
        if (t < 64) {
            unsigned long long w = g_maskT[g][base + t];
            s_col[t] = w;
            if (w) atomicOr(&s_colOR, w);
        } else if (t < 128) {
            s_gnext[t - 64] = haveNext ? g_maskT[g + 1][base + (t - 64)] : 0ull;
        } else if (haveNext) {
            unsigned long long p = 0ull;
            for (int r = t - 128; r < base; r += 128)
                if ((s_alive[r >> 6] >> (r & 63)) & 1ull) p |= g_maskT[g + 1][r];
            if (p) atomicOr(&s_crossbuf[nxt], p);
        }
        __syncthreads();
        // ---- Phase B: decision
        unsigned long long cross = s_crossbuf[cur];
        unsigned long long colOR = s_colOR;
        unsigned long long rowmask = (n == 64) ? ~0ull : ((1ull << n) - 1ull);
        bool fast = (cross == 0ull && colOR == 0ull && kcount + n <= NPOST);
        if (fast) {
            if (t < n) s_kept[kcount + t] = base + t;
            if (t == 0) { s_kc = kcount + n; s_alivew = rowmask; }
        } else if (t == 0) {
            unsigned long long avail = (~cross) & rowmask;
            unsigned long long alivew = 0ull;
            int kc = kcount;
            while (avail && kc < NPOST) {
                int k1 = __ffsll((long long)avail) - 1;
                unsigned long long r = avail & (avail - 1);
                unsigned long long c1 = s_col[k1];
                int k2 = -1, k3 = -1, k4 = -1;
                unsigned long long c2 = 0, c3 = 0, c4 = 0;
                if (r) { k2 = __ffsll((long long)r) - 1; c2 = s_col[k2]; r &= r - 1;
                    if (r) { k3 = __ffsll((long long)r) - 1; c3 = s_col[k3]; r &= r - 1;
                        if (r) { k4 = __ffsll((long long)r) - 1; c4 = s_col[k4]; r &= r - 1; } } }
                unsigned long long m = c1;
                s_kept[kc++] = base + k1; alivew |= 1ull << k1;
                if (k2 >= 0 && kc < NPOST && !((m >> k2) & 1ull)) { s_kept[kc++] = base + k2; alivew |= 1ull << k2; m |= c2; }
                if (k3 >= 0 && kc < NPOST && !((m >> k3) & 1ull)) { s_kept[kc++] = base + k3; alivew |= 1ull << k3; m |= c3; }
                if (k4 >= 0 && kc < NPOST && !((m >> k4) & 1ull)) { s_kept[kc++] = base + k4; alivew |= 1ull << k4; m |= c4; }
                avail = r & ~m;
            }
            s_kc = kc; s_alivew = alivew;
        }
        __syncthreads();
        // ---- Phase C: combine + bookkeeping
        kcount = s_kc;
        unsigned long long aw = s_alivew;
        if (t < 64 && ((aw >> t) & 1ull)) {
            unsigned long long w = s_gnext[t];
            if (w) atomicOr(&s_crossbuf[nxt], w);
        }
        if (t == 0) { s_alive[g] = aw; s_crossbuf[cur] = 0ull; s_colOR = 0ull; }
        __syncthreads();
        if (kcount >= NPOST) break;
    }
    // epilogue
    int kc0 = g_kcount;
    for (int i = kc0 + t; i < kcount; i += 256) g_kept[i] = s_kept[i];
    for (int i = t; i < NB; i += 256) g_alive[i] = s_alive[i];
    if (t == 0) {
        g_kcount = kcount;
        if (kcount >= NPOST || g1 >= NB) g_done = 1;
    }
}

// ---------------- K8: write output ------------------------------------------
__global__ void out_k(float* __restrict__ out) {
    int kcount = g_kcount;
    int o = blockIdx.x * blockDim.x + threadIdx.x;
    if (o < NPOST) {
        if (o < kcount) {
            int i = g_kept[o];
            ((float4*)out)[o] = make_float4(g_y1[i], g_x1[i], g_y2[i], g_x2[i]);
            out[NPOST * 4 + o] = g_scores[i];
        } else {
            ((float4*)out)[o] = make_float4(0.f, 0.f, 0.f, 0.f);
            out[NPOST * 4 + o] = 0.f;
        }
    }
}

// ---------------- launch ----------------------------------------------------
extern "C" void kernel_launch(void* const* d_in, const int* in_sizes, int n_in,
                              void* d_out, int out_size) {
    const float* enc    = (const float*)d_in[0];  // encoded_bboxes [N,4]
    const float* anch   = (const float*)d_in[1];  // anchors        [N,4]
    const float* scores = (const float*)d_in[2];  // scores         [N]
    float* out = (float*)d_out;                   // 2000*4 boxes + 2000 scores
    int n = in_sizes[2];
    int n4 = n / 4;

    zero_k<<<(HB + 255) / 256, 256>>>();
    hist_stash_k<<<1024, 256>>>((const float4*)scores, n4);
    thresh_k<<<1, 1024>>>();
    compact_k<<<512, 256>>>((const float4*)scores, n4);
    bsort_decode_k<<<148, 128>>>(enc, anch, n);

    // chunked mask+NMS with early-exit flag; expected exit ~group 33-35
    mask_k<<<dim3(36, 36), 64>>>(0);
    nms_part_k<<<1, 256>>>(0, 36);
    mask_k<<<dim3(24, 60), 64>>>(36);
    nms_part_k<<<1, 256>>>(36, 60);
    mask_k<<<dim3(34, 94), 64>>>(60);
    nms_part_k<<<1, 256>>>(60, 94);

    out_k<<<(NPOST + 255) / 256, 256>>>(out);
}